// round 6
// baseline (speedup 1.0000x reference)
#include <cuda_runtime.h>
#include <cuda_bf16.h>
#include <cstdint>

#define DIMS 64
#define TPB 256
#define MAXBLOCKS 8192

// Dynamic SMEM: X tile @0 (256x128B bf16 SW128), codebook @32768 (1024x128B),
// stage @163840 (8 warps x 4608B: 32 rows x 36 floats, half-tile staging).
#define SM_X 0
#define SM_CB 32768
#define SM_STG 163840
#define STG_WARP 4608
#define STG_STRIDE 36
#define SMEM_TOTAL (163840 + 8 * STG_WARP)

#define MARGIN_D 1e-3f

__device__ double g_partials[MAXBLOCKS];

__device__ __forceinline__ uint32_t smem_u32(const void* p) {
    uint32_t a;
    asm("{ .reg .u64 t; cvta.to.shared.u64 t, %1; cvt.u32.u64 %0, t; }"
        : "=r"(a) : "l"(p));
    return a;
}
__device__ __forceinline__ uint32_t swz(uint32_t off) {
    return off ^ ((off >> 3) & 0x70);   // SW128: bits[4:6] ^= row bits[7:9]
}
__device__ __forceinline__ uint32_t bf2(float a, float b) {
    __nv_bfloat162 t = __floats2bfloat162_rn(a, b);
    return *(uint32_t*)&t;
}
#define LDSM_X4(r0, r1, r2, r3, a) \
    asm volatile("ldmatrix.sync.aligned.m8n8.x4.shared.b16 {%0,%1,%2,%3}, [%4];" \
                 : "=r"(r0), "=r"(r1), "=r"(r2), "=r"(r3) : "r"(a))
#define MMA16816(c, a, b) \
    asm volatile("mma.sync.aligned.m16n8k16.row.col.f32.bf16.bf16.f32 " \
                 "{%0,%1,%2,%3}, {%4,%5,%6,%7}, {%8,%9}, {%0,%1,%2,%3};" \
                 : "+f"((c)[0]), "+f"((c)[1]), "+f"((c)[2]), "+f"((c)[3]) \
                 : "r"((a)[0]), "r"((a)[1]), "r"((a)[2]), "r"((a)[3]), \
                   "r"((b)[0]), "r"((b)[1]))

// ---------------------------------------------------------------------------
// Pass 1 (bf16 HMMA): d-tilde = x.e for all 1024 codes, per-point top-8.
// Pass 2 (exact fp32): rescore candidates within MARGIN_D of the best d-tilde
// replicating JAX rounding exactly (validated R1/R3: 0 argmin flips).
// ---------------------------------------------------------------------------
__global__ __launch_bounds__(TPB, 1)
void vq_hmma(const float* __restrict__ x, const float* __restrict__ cb,
             float* __restrict__ out, int N, int K) {
    extern __shared__ char smem[];
    const uint32_t sb = smem_u32(smem);
    const int tid = threadIdx.x;
    const int w = tid >> 5, lane = tid & 31;
    const int g = lane >> 2, tig = lane & 3;
    const int n = blockIdx.x * TPB + w * 32 + lane;   // this thread's point
    const bool active = (n < N);
    const int ntiles = K >> 6;                        // 64 codes per tile

    // --- Fill X tile (256 pts x 64 dims, bf16, SW128) ----------------------
    {
        const int pb = blockIdx.x * TPB;
        for (int c = tid; c < TPB * 8; c += TPB) {
            int row = c >> 3, sub = c & 7, pn = pb + row;
            float4 f0 = {0, 0, 0, 0}, f1 = {0, 0, 0, 0};
            if (pn < N) {
                const float4* gp = (const float4*)(x + (size_t)pn * DIMS + sub * 8);
                f0 = gp[0]; f1 = gp[1];
            }
            uint4 v = { bf2(f0.x, f0.y), bf2(f0.z, f0.w),
                        bf2(f1.x, f1.y), bf2(f1.z, f1.w) };
            *(uint4*)(smem + SM_X + swz(row * 128 + sub * 16)) = v;
        }
        // --- Fill codebook (K x 64 dims, bf16, SW128) ----------------------
        for (int c = tid; c < K * 8; c += TPB) {
            int row = c >> 3, sub = c & 7;
            const float4* gp = (const float4*)(cb + (size_t)row * DIMS + sub * 8);
            float4 f0 = gp[0], f1 = gp[1];
            uint4 v = { bf2(f0.x, f0.y), bf2(f0.z, f0.w),
                        bf2(f1.x, f1.y), bf2(f1.z, f1.w) };
            *(uint4*)(smem + SM_CB + swz(row * 128 + sub * 16)) = v;
        }
    }
    __syncthreads();

    // --- A fragments: this warp's 32 points, K=64, resident all kernel -----
    uint32_t afr[2][4][4];
    {
        const int wbase = w * 32;
#pragma unroll
        for (int mt = 0; mt < 2; mt++)
#pragma unroll
            for (int kt = 0; kt < 4; kt++) {
                int row = wbase + mt * 16 + (lane & 15);
                int c16 = kt * 2 + (lane >> 4);
                uint32_t a = sb + SM_X + swz(row * 128 + c16 * 16);
                LDSM_X4(afr[mt][kt][0], afr[mt][kt][1],
                        afr[mt][kt][2], afr[mt][kt][3], a);
            }
    }

    float cd[8]; int ck[8];
#pragma unroll
    for (int i = 0; i < 8; i++) { cd[i] = -3.402823466e38f; ck[i] = 0; }
    float m8 = -3.402823466e38f;

    float* stg = (float*)(smem + SM_STG + w * STG_WARP);

    for (int t = 0; t < ntiles; t++) {
        float acc[2][8][4];
#pragma unroll
        for (int mt = 0; mt < 2; mt++)
#pragma unroll
            for (int ns = 0; ns < 8; ns++)
#pragma unroll
                for (int i = 0; i < 4; i++) acc[mt][ns][i] = 0.f;

#pragma unroll
        for (int kt = 0; kt < 4; kt++) {
            uint32_t bfr[8][2];
#pragma unroll
            for (int np = 0; np < 4; np++) {
                int row = t * 64 + np * 16 + (lane & 7) + ((lane & 16) ? 8 : 0);
                int c16 = kt * 2 + ((lane >> 3) & 1);
                uint32_t a = sb + SM_CB + swz(row * 128 + c16 * 16);
                LDSM_X4(bfr[2 * np][0], bfr[2 * np][1],
                        bfr[2 * np + 1][0], bfr[2 * np + 1][1], a);
            }
#pragma unroll
            for (int mt = 0; mt < 2; mt++)
#pragma unroll
                for (int ns = 0; ns < 8; ns++)
                    MMA16816(acc[mt][ns], afr[mt][kt], bfr[ns]);
        }

        // Stage + scan in two 32-col halves (stride-36 layout: conflict-free
        // LDS.128 within each 8-lane phase; 2-way worst case on stores).
#pragma unroll
        for (int half = 0; half < 2; half++) {
            __syncwarp();
#pragma unroll
            for (int mt = 0; mt < 2; mt++)
#pragma unroll
                for (int nsl = 0; nsl < 4; nsl++) {
                    int ns = half * 4 + nsl;
                    int r0 = mt * 16 + g, col = nsl * 8 + 2 * tig;
                    stg[r0 * STG_STRIDE + col]           = acc[mt][ns][0];
                    stg[r0 * STG_STRIDE + col + 1]       = acc[mt][ns][1];
                    stg[(r0 + 8) * STG_STRIDE + col]     = acc[mt][ns][2];
                    stg[(r0 + 8) * STG_STRIDE + col + 1] = acc[mt][ns][3];
                }
            __syncwarp();
            int kb = t * 64 + half * 32;
#pragma unroll
            for (int cc = 0; cc < 8; cc++) {
                float4 v = *(float4*)(stg + lane * STG_STRIDE + cc * 4);
                float dv[4] = { v.x, v.y, v.z, v.w };
#pragma unroll
                for (int j = 0; j < 4; j++) {
                    float d = dv[j];
                    if (d > m8) {
                        bool done = false;
#pragma unroll
                        for (int i = 0; i < 8; i++)
                            if (!done && cd[i] == m8) {
                                cd[i] = d; ck[i] = kb + cc * 4 + j; done = true;
                            }
                        m8 = cd[0];
#pragma unroll
                        for (int i = 1; i < 8; i++) m8 = fminf(m8, cd[i]);
                    }
                }
            }
        }
    }

    // --- Exact rescore (replicates JAX fp32 rounding), output, loss --------
    double lsum = 0.0;
    if (active) {
        float4 xr[DIMS / 4];
        const float4* xrow = (const float4*)(x + (size_t)n * DIMS);
#pragma unroll
        for (int j = 0; j < DIMS / 4; j++) xr[j] = xrow[j];
        float A = 0.f;                         // sequential non-FMA ||x||^2
#pragma unroll
        for (int j = 0; j < DIMS / 4; j++) {
            A = __fadd_rn(A, __fmul_rn(xr[j].x, xr[j].x));
            A = __fadd_rn(A, __fmul_rn(xr[j].y, xr[j].y));
            A = __fadd_rn(A, __fmul_rn(xr[j].z, xr[j].z));
            A = __fadd_rn(A, __fmul_rn(xr[j].w, xr[j].w));
        }
        float dmax = cd[0];
#pragma unroll
        for (int i = 1; i < 8; i++) dmax = fmaxf(dmax, cd[i]);
        const float thr = dmax - MARGIN_D;

        float bsc = 3.402823466e38f; int bk = 0x7fffffff;
#pragma unroll
        for (int slot = 0; slot < 8; slot++) {
            if (cd[slot] >= thr) {
                int k = ck[slot];
                const float4* e4 = (const float4*)(cb + (size_t)k * DIMS);
                float c = 0.f, p0 = 0.f, p1 = 0.f, p2 = 0.f, p3 = 0.f;
#pragma unroll
                for (int j = 0; j < DIMS / 4; j++) {
                    float4 e = e4[j];
                    c = __fadd_rn(c, __fmul_rn(e.x, e.x));
                    c = __fadd_rn(c, __fmul_rn(e.y, e.y));
                    c = __fadd_rn(c, __fmul_rn(e.z, e.z));
                    c = __fadd_rn(c, __fmul_rn(e.w, e.w));
                    p0 = fmaf(xr[j].x, e.x, p0);
                    p1 = fmaf(xr[j].y, e.y, p1);
                    p2 = fmaf(xr[j].z, e.z, p2);
                    p3 = fmaf(xr[j].w, e.w, p3);
                }
                float d = __fadd_rn(__fadd_rn(p0, p1), __fadd_rn(p2, p3));
                float s = __fadd_rn(__fsub_rn(A, 2.0f * d), c);
                if (s < bsc || (s == bsc && k < bk)) { bsc = s; bk = k; }
            }
        }
        const float4* q4 = (const float4*)(cb + (size_t)bk * DIMS);
        float4* o4 = (float4*)(out + (size_t)n * DIMS);
        float ls = 0.f;
#pragma unroll
        for (int j = 0; j < DIMS / 4; j++) {
            float4 q = q4[j];
            o4[j] = q;
            float dx = __fsub_rn(q.x, xr[j].x); ls = __fadd_rn(ls, __fmul_rn(dx, dx));
            float dy = __fsub_rn(q.y, xr[j].y); ls = __fadd_rn(ls, __fmul_rn(dy, dy));
            float dz = __fsub_rn(q.z, xr[j].z); ls = __fadd_rn(ls, __fmul_rn(dz, dz));
            float dw = __fsub_rn(q.w, xr[j].w); ls = __fadd_rn(ls, __fmul_rn(dw, dw));
        }
        lsum = (double)ls;
    }

    // Deterministic per-CTA fp64 reduction (reuse dynamic smem, now dead).
    __syncthreads();
    double* red = (double*)smem;
    red[tid] = lsum;
    __syncthreads();
    for (int s = TPB / 2; s > 0; s >>= 1) {
        if (tid < s) red[tid] += red[tid + s];
        __syncthreads();
    }
    if (tid == 0) g_partials[blockIdx.x] = red[0];
}

// --------------------------------------------------------------------------
__global__ void vq_finalize(float* __restrict__ out, int nblocks,
                            long long total, int loss_off) {
    __shared__ double r[256];
    double s = 0.0;
    for (int i = threadIdx.x; i < nblocks; i += 256) s += g_partials[i];
    r[threadIdx.x] = s;
    __syncthreads();
    for (int st = 128; st > 0; st >>= 1) {
        if (threadIdx.x < st) r[threadIdx.x] += r[threadIdx.x + st];
        __syncthreads();
    }
    if (threadIdx.x == 0) {
        float m = (float)(r[0] / (double)total);
        out[loss_off] = __fadd_rn(m, __fmul_rn(0.25f, m));
    }
}

// --------------------------------------------------------------------------
extern "C" void kernel_launch(void* const* d_in, const int* in_sizes, int n_in,
                              void* d_out, int out_size) {
    const float* x  = (const float*)d_in[0];   // [32,4096,64] fp32
    const float* cb = (const float*)d_in[1];   // [1024,64]    fp32
    float* out = (float*)d_out;

    const int ND = in_sizes[0];
    const int N = ND / DIMS;
    const int K = in_sizes[1] / DIMS;

    int nb = (N + TPB - 1) / TPB;
    if (nb > MAXBLOCKS) nb = MAXBLOCKS;

    cudaFuncSetAttribute(vq_hmma, cudaFuncAttributeMaxDynamicSharedMemorySize,
                         SMEM_TOTAL);
    vq_hmma<<<nb, TPB, SMEM_TOTAL>>>(x, cb, out, N, K);
    vq_finalize<<<1, 256>>>(out, nb, (long long)ND, ND);
}

// round 9
// speedup vs baseline: 1.0066x; 1.0066x over previous
#include <cuda_runtime.h>
#include <cuda_bf16.h>
#include <cstdint>

#define DIMS 64
#define TPB 512
#define PTS 512
#define MAXBLOCKS 8192
#define CANDS 8

// Dynamic SMEM: X tile @0 (512x128B bf16 SW128; region reused after fragment
// load for cnt/cand/red), codebook @65536 (1024x128B bf16 SW128).
#define SM_X 0
#define SM_CB 65536
#define SM_CNT 0              /* 512 u32   (reuses X region)       */
#define SM_CAND 2048          /* 512x8 u32                          */
#define SM_RED 18432          /* 512 doubles                        */
#define SMEM_TOTAL (65536 + 131072)

#define MARGIN_D 1e-3f

__device__ double g_partials[MAXBLOCKS];

__device__ __forceinline__ uint32_t smem_u32(const void* p) {
    uint32_t a;
    asm("{ .reg .u64 t; cvta.to.shared.u64 t, %1; cvt.u32.u64 %0, t; }"
        : "=r"(a) : "l"(p));
    return a;
}
__device__ __forceinline__ uint32_t swz(uint32_t off) {
    return off ^ ((off >> 3) & 0x70);   // SW128
}
__device__ __forceinline__ uint32_t bf2(float a, float b) {
    __nv_bfloat162 t = __floats2bfloat162_rn(a, b);
    return *(uint32_t*)&t;
}
#define LDSM_X4(r0, r1, r2, r3, a) \
    asm volatile("ldmatrix.sync.aligned.m8n8.x4.shared.b16 {%0,%1,%2,%3}, [%4];" \
                 : "=r"(r0), "=r"(r1), "=r"(r2), "=r"(r3) : "r"(a))
#define MMA16816(c, a, b) \
    asm volatile("mma.sync.aligned.m16n8k16.row.col.f32.bf16.bf16.f32 " \
                 "{%0,%1,%2,%3}, {%4,%5,%6,%7}, {%8,%9}, {%0,%1,%2,%3};" \
                 : "+f"((c)[0]), "+f"((c)[1]), "+f"((c)[2]), "+f"((c)[3]) \
                 : "r"((a)[0]), "r"((a)[1]), "r"((a)[2]), "r"((a)[3]), \
                   "r"((b)[0]), "r"((b)[1]))

// One 32-code MMA tile: acc[mt][ns][0..3] for rows {mt*16+g, mt*16+g+8} and
// cols {ns*8 + 2*tig + 0/1}. Deterministic: pass 1 and pass 2 produce
// bit-identical d-tilde.
__device__ __forceinline__ void mma_tile(float acc[2][4][4],
                                         const uint32_t afr[2][4][4],
                                         uint32_t sb, int t, int lane) {
#pragma unroll
    for (int mt = 0; mt < 2; mt++)
#pragma unroll
        for (int ns = 0; ns < 4; ns++)
#pragma unroll
            for (int i = 0; i < 4; i++) acc[mt][ns][i] = 0.f;
#pragma unroll
    for (int kt = 0; kt < 4; kt++) {
        uint32_t bfr[4][2];
#pragma unroll
        for (int np = 0; np < 2; np++) {
            int row = t * 32 + np * 16 + (lane & 7) + ((lane & 16) ? 8 : 0);
            int c16 = kt * 2 + ((lane >> 3) & 1);
            uint32_t a = sb + SM_CB + swz(row * 128 + c16 * 16);
            LDSM_X4(bfr[2 * np][0], bfr[2 * np][1],
                    bfr[2 * np + 1][0], bfr[2 * np + 1][1], a);
        }
#pragma unroll
        for (int mt = 0; mt < 2; mt++)
#pragma unroll
            for (int ns = 0; ns < 4; ns++)
                MMA16816(acc[mt][ns], afr[mt][kt], bfr[ns]);
    }
}

// ---------------------------------------------------------------------------
// Pass 1: HMMA d-tilde, per-point running MAX (branchless fmax, no staging).
// Pass 2: recompute HMMA; collect codes with d-tilde >= max - margin into
//         per-point smem candidate lists (avg 1.3 hits/point, ballot-guarded).
// Pass 3: exact fp32 rescore replicating JAX rounding (validated: rel_err
//         4.368407e-05 with ZERO argmin flips in R1/R3/R6).
// ---------------------------------------------------------------------------
__global__ __launch_bounds__(TPB, 1)
void vq_hmma(const float* __restrict__ x, const float* __restrict__ cb,
             float* __restrict__ out, int N, int K) {
    extern __shared__ char smem[];
    const uint32_t sb = smem_u32(smem);
    const int tid = threadIdx.x;
    const int w = tid >> 5, lane = tid & 31;
    const int g = lane >> 2, tig = lane & 3;
    const int n = blockIdx.x * PTS + tid;
    const bool active = (n < N);
    const int ntiles = K >> 5;                 // 32 codes per tile

    uint32_t* s_cnt  = (uint32_t*)(smem + SM_CNT);
    uint32_t* s_cand = (uint32_t*)(smem + SM_CAND);

    // --- Fill X (512 pts) and codebook (K codes), bf16 SW128 ---------------
    {
        const int pb = blockIdx.x * PTS;
        for (int c = tid; c < PTS * 8; c += TPB) {
            int row = c >> 3, sub = c & 7, pn = pb + row;
            float4 f0 = {0, 0, 0, 0}, f1 = {0, 0, 0, 0};
            if (pn < N) {
                const float4* gp = (const float4*)(x + (size_t)pn * DIMS + sub * 8);
                f0 = gp[0]; f1 = gp[1];
            }
            uint4 v = { bf2(f0.x, f0.y), bf2(f0.z, f0.w),
                        bf2(f1.x, f1.y), bf2(f1.z, f1.w) };
            *(uint4*)(smem + SM_X + swz(row * 128 + sub * 16)) = v;
        }
        for (int c = tid; c < K * 8; c += TPB) {
            int row = c >> 3, sub = c & 7;
            const float4* gp = (const float4*)(cb + (size_t)row * DIMS + sub * 8);
            float4 f0 = gp[0], f1 = gp[1];
            uint4 v = { bf2(f0.x, f0.y), bf2(f0.z, f0.w),
                        bf2(f1.x, f1.y), bf2(f1.z, f1.w) };
            *(uint4*)(smem + SM_CB + swz(row * 128 + sub * 16)) = v;
        }
    }
    __syncthreads();

    // --- A fragments: this warp's 32 points, K=64, resident in registers ---
    uint32_t afr[2][4][4];
#pragma unroll
    for (int mt = 0; mt < 2; mt++)
#pragma unroll
        for (int kt = 0; kt < 4; kt++) {
            int row = w * 32 + mt * 16 + (lane & 15);
            int c16 = kt * 2 + (lane >> 4);
            uint32_t a = sb + SM_X + swz(row * 128 + c16 * 16);
            LDSM_X4(afr[mt][kt][0], afr[mt][kt][1],
                    afr[mt][kt][2], afr[mt][kt][3], a);
        }
    __syncthreads();                           // X region now reusable

    // Zero candidate counters (X region reuse).
    for (int i = tid; i < PTS; i += TPB) s_cnt[i] = 0;

    // --- Pass 1: running row max of d-tilde --------------------------------
    // Row-slot map: slot 2*mt+h -> row w*32 + mt*16 + g + 8*h.
    float rm[4] = { -3.402823466e38f, -3.402823466e38f,
                    -3.402823466e38f, -3.402823466e38f };
    for (int t = 0; t < ntiles; t++) {
        float acc[2][4][4];
        mma_tile(acc, afr, sb, t, lane);
#pragma unroll
        for (int mt = 0; mt < 2; mt++)
#pragma unroll
            for (int ns = 0; ns < 4; ns++) {
                rm[2 * mt]     = fmaxf(rm[2 * mt],
                                       fmaxf(acc[mt][ns][0], acc[mt][ns][1]));
                rm[2 * mt + 1] = fmaxf(rm[2 * mt + 1],
                                       fmaxf(acc[mt][ns][2], acc[mt][ns][3]));
            }
    }
    // Combine across the 4 lanes (tig) sharing each row.
    float thr[4];
#pragma unroll
    for (int i = 0; i < 4; i++) {
        float v = rm[i];
        v = fmaxf(v, __shfl_xor_sync(0xffffffffu, v, 1));
        v = fmaxf(v, __shfl_xor_sync(0xffffffffu, v, 2));
        thr[i] = v - MARGIN_D;
    }
    __syncthreads();                           // cnt zeroing visible

    // --- Pass 2: recompute, collect margin candidates ----------------------
    for (int t = 0; t < ntiles; t++) {
        float acc[2][4][4];
        mma_tile(acc, afr, sb, t, lane);
        bool any = false;
#pragma unroll
        for (int mt = 0; mt < 2; mt++)
#pragma unroll
            for (int ns = 0; ns < 4; ns++) {
                any |= (acc[mt][ns][0] >= thr[2 * mt]);
                any |= (acc[mt][ns][1] >= thr[2 * mt]);
                any |= (acc[mt][ns][2] >= thr[2 * mt + 1]);
                any |= (acc[mt][ns][3] >= thr[2 * mt + 1]);
            }
        if (__ballot_sync(0xffffffffu, any)) {
#pragma unroll
            for (int mt = 0; mt < 2; mt++)
#pragma unroll
                for (int ns = 0; ns < 4; ns++)
#pragma unroll
                    for (int c = 0; c < 4; c++) {
                        int h = c >> 1;
                        if (acc[mt][ns][c] >= thr[2 * mt + h]) {
                            int row = w * 32 + mt * 16 + g + 8 * h;
                            uint32_t k = t * 32 + ns * 8 + 2 * tig + (c & 1);
                            uint32_t idx = atomicAdd(&s_cnt[row], 1u);
                            if (idx < CANDS) s_cand[row * CANDS + idx] = k;
                        }
                    }
        }
    }
    __syncthreads();

    // --- Pass 3: exact rescore (JAX fp32 rounding replica), output, loss ---
    double lsum = 0.0;
    if (active) {
        float4 xr[DIMS / 4];
        const float4* xrow = (const float4*)(x + (size_t)n * DIMS);
#pragma unroll
        for (int j = 0; j < DIMS / 4; j++) xr[j] = xrow[j];
        float A = 0.f;                         // sequential non-FMA ||x||^2
#pragma unroll
        for (int j = 0; j < DIMS / 4; j++) {
            A = __fadd_rn(A, __fmul_rn(xr[j].x, xr[j].x));
            A = __fadd_rn(A, __fmul_rn(xr[j].y, xr[j].y));
            A = __fadd_rn(A, __fmul_rn(xr[j].z, xr[j].z));
            A = __fadd_rn(A, __fmul_rn(xr[j].w, xr[j].w));
        }
        uint32_t nc = s_cnt[tid];
        bool overflow = (nc > CANDS);          // statistically unreachable
        if (overflow) nc = 0;

        float bsc = 3.402823466e38f; int bk = 0x7fffffff;
        for (uint32_t it = 0; it < (overflow ? (uint32_t)K : nc); it++) {
            int k = overflow ? (int)it : (int)s_cand[tid * CANDS + it];
            const float4* e4 = (const float4*)(cb + (size_t)k * DIMS);
            float c = 0.f, p0 = 0.f, p1 = 0.f, p2 = 0.f, p3 = 0.f;
#pragma unroll
            for (int j = 0; j < DIMS / 4; j++) {
                float4 e = e4[j];
                c = __fadd_rn(c, __fmul_rn(e.x, e.x));
                c = __fadd_rn(c, __fmul_rn(e.y, e.y));
                c = __fadd_rn(c, __fmul_rn(e.z, e.z));
                c = __fadd_rn(c, __fmul_rn(e.w, e.w));
                p0 = fmaf(xr[j].x, e.x, p0);
                p1 = fmaf(xr[j].y, e.y, p1);
                p2 = fmaf(xr[j].z, e.z, p2);
                p3 = fmaf(xr[j].w, e.w, p3);
            }
            float d = __fadd_rn(__fadd_rn(p0, p1), __fadd_rn(p2, p3));
            float s = __fadd_rn(__fsub_rn(A, 2.0f * d), c);
            if (s < bsc || (s == bsc && k < bk)) { bsc = s; bk = k; }
        }
        const float4* q4 = (const float4*)(cb + (size_t)bk * DIMS);
        float4* o4 = (float4*)(out + (size_t)n * DIMS);
        float ls = 0.f;
#pragma unroll
        for (int j = 0; j < DIMS / 4; j++) {
            float4 q = q4[j];
            o4[j] = q;
            float dx = __fsub_rn(q.x, xr[j].x); ls = __fadd_rn(ls, __fmul_rn(dx, dx));
            float dy = __fsub_rn(q.y, xr[j].y); ls = __fadd_rn(ls, __fmul_rn(dy, dy));
            float dz = __fsub_rn(q.z, xr[j].z); ls = __fadd_rn(ls, __fmul_rn(dz, dz));
            float dw = __fsub_rn(q.w, xr[j].w); ls = __fadd_rn(ls, __fmul_rn(dw, dw));
        }
        lsum = (double)ls;
    }

    // Deterministic per-CTA fp64 reduction.
    __syncthreads();
    double* red = (double*)(smem + SM_RED);
    red[tid] = lsum;
    __syncthreads();
    for (int s = TPB / 2; s > 0; s >>= 1) {
        if (tid < s) red[tid] += red[tid + s];
        __syncthreads();
    }
    if (tid == 0) g_partials[blockIdx.x] = red[0];
}

// --------------------------------------------------------------------------
__global__ void vq_finalize(float* __restrict__ out, int nblocks,
                            long long total, int loss_off) {
    __shared__ double r[256];
    double s = 0.0;
    for (int i = threadIdx.x; i < nblocks; i += 256) s += g_partials[i];
    r[threadIdx.x] = s;
    __syncthreads();
    for (int st = 128; st > 0; st >>= 1) {
        if (threadIdx.x < st) r[threadIdx.x] += r[threadIdx.x + st];
        __syncthreads();
    }
    if (threadIdx.x == 0) {
        float m = (float)(r[0] / (double)total);
        out[loss_off] = __fadd_rn(m, __fmul_rn(0.25f, m));
    }
}

// --------------------------------------------------------------------------
extern "C" void kernel_launch(void* const* d_in, const int* in_sizes, int n_in,
                              void* d_out, int out_size) {
    const float* x  = (const float*)d_in[0];   // [32,4096,64] fp32
    const float* cb = (const float*)d_in[1];   // [1024,64]    fp32
    float* out = (float*)d_out;

    const int ND = in_sizes[0];
    const int N = ND / DIMS;
    const int K = in_sizes[1] / DIMS;

    int nb = (N + PTS - 1) / PTS;              // 256 CTAs for this shape
    if (nb > MAXBLOCKS) nb = MAXBLOCKS;

    cudaFuncSetAttribute(vq_hmma, cudaFuncAttributeMaxDynamicSharedMemorySize,
                         SMEM_TOTAL);
    vq_hmma<<<nb, TPB, SMEM_TOTAL>>>(x, cb, out, N, K);
    vq_finalize<<<1, 256>>>(out, nb, (long long)ND, ND);
}

// round 11
// speedup vs baseline: 3.8560x; 3.8307x over previous
#include <cuda_runtime.h>
#include <cstdint>

#define DIMS 64
#define TPB 256
#define CANDS 16
#define MAXBLOCKS 8192

__device__ float  g_escale;
__device__ double g_partials[MAXBLOCKS];

// ---------------------------------------------------------------------------
// Kernel 1: global max |e| over the codebook (fp32 max is exact/deterministic).
// ---------------------------------------------------------------------------
__global__ void vq_escale_k(const float* __restrict__ cb, int KD) {
    __shared__ float r[256];
    float m = 0.f;
    for (int i = threadIdx.x; i < KD; i += 256)
        m = fmaxf(m, fabsf(cb[i]));
    r[threadIdx.x] = m;
    __syncthreads();
    for (int s = 128; s > 0; s >>= 1) {
        if (threadIdx.x < s)
            r[threadIdx.x] = fmaxf(r[threadIdx.x], r[threadIdx.x + s]);
        __syncthreads();
    }
    if (threadIdx.x == 0) g_escale = r[0];
}

// 64-dim int8 dot via 16 DP4A (exact integer arithmetic; |q|<=127 so the
// accumulator max 64*127^2 ~ 1.03e6 is far from overflow).
__device__ __forceinline__ int dotq(const int4* __restrict__ cbq,
                                    const int xq[16], int k) {
    int s0 = 0, s1 = 0, s2 = 0, s3 = 0;
#pragma unroll
    for (int i = 0; i < 4; i++) {
        int4 v = cbq[k * 4 + i];
        s0 = __dp4a(xq[4 * i + 0], v.x, s0);
        s1 = __dp4a(xq[4 * i + 1], v.y, s1);
        s2 = __dp4a(xq[4 * i + 2], v.z, s2);
        s3 = __dp4a(xq[4 * i + 3], v.w, s3);
    }
    return (s0 + s1) + (s2 + s3);
}

// ---------------------------------------------------------------------------
// Filter: int8 DP4A d-tilde, running-threshold collection. On list overflow,
// an int SALVAGE pass recollects with the final threshold (count then = codes
// within margin of the true max, ~1.6 expected; overflow beyond that is
// statistically unreachable but still falls back to exhaustive exact scan).
// Rescore: exact fp32 JAX-rounding replica (validated: rel_err 4.368407e-05,
// zero argmin flips, R1/R3/R6/R9).
// ---------------------------------------------------------------------------
__global__ __launch_bounds__(TPB, 2)
void vq_dp4a(const float* __restrict__ x, const float* __restrict__ cb,
             float* __restrict__ out, int N, int K) {
    extern __shared__ char smem[];
    const int4* cbq   = (const int4*)smem;                  // K*64 int8
    uint16_t* s_cand  = (uint16_t*)(smem + (size_t)K * DIMS);
    double*   red     = (double*)(smem + (size_t)K * DIMS + TPB * CANDS * 2);

    const int tid = threadIdx.x;
    const int n = blockIdx.x * TPB + tid;
    const bool active = (n < N);

    const float esc = g_escale;
    const float se = fmaxf(esc, 1e-20f) / 127.f;
    const float inv_se = 1.f / se;

    // --- Quantize codebook into SMEM int8 (byte order matches xq packing) --
    for (int i = tid; i < K * (DIMS / 4); i += TPB) {
        float4 v = ((const float4*)cb)[i];
        int q0 = __float2int_rn(v.x * inv_se);
        int q1 = __float2int_rn(v.y * inv_se);
        int q2 = __float2int_rn(v.z * inv_se);
        int q3 = __float2int_rn(v.w * inv_se);
        ((int*)smem)[i] = (q0 & 255) | ((q1 & 255) << 8) |
                          ((q2 & 255) << 16) | (q3 << 24);
    }

    // --- Own point: exact-sequential A (validated order), maxabs, quantize --
    float A = 0.f, mx = 0.f;
    int xq[16];
    float sx = 1.f;
    if (active) {
        const float4* xrow = (const float4*)(x + (size_t)n * DIMS);
        float4 xr[16];
#pragma unroll
        for (int j = 0; j < 16; j++) xr[j] = xrow[j];
#pragma unroll
        for (int j = 0; j < 16; j++) {
            A = __fadd_rn(A, __fmul_rn(xr[j].x, xr[j].x));
            A = __fadd_rn(A, __fmul_rn(xr[j].y, xr[j].y));
            A = __fadd_rn(A, __fmul_rn(xr[j].z, xr[j].z));
            A = __fadd_rn(A, __fmul_rn(xr[j].w, xr[j].w));
            mx = fmaxf(mx, fmaxf(fmaxf(fabsf(xr[j].x), fabsf(xr[j].y)),
                                 fmaxf(fabsf(xr[j].z), fabsf(xr[j].w))));
        }
        sx = fmaxf(mx, 1e-20f) / 127.f;
        float inv_sx = 1.f / sx;
#pragma unroll
        for (int j = 0; j < 16; j++) {
            int q0 = __float2int_rn(xr[j].x * inv_sx);
            int q1 = __float2int_rn(xr[j].y * inv_sx);
            int q2 = __float2int_rn(xr[j].z * inv_sx);
            int q3 = __float2int_rn(xr[j].w * inv_sx);
            xq[j] = (q0 & 255) | ((q1 & 255) << 8) |
                    ((q2 & 255) << 16) | (q3 << 24);
        }
    } else {
#pragma unroll
        for (int j = 0; j < 16; j++) xq[j] = 0;
    }
    __syncthreads();

    // --- Margin in integer d-tilde units (>=8-sigma quantization-error model
    //     with 2x variance headroom, + ||e||^2/2 ranking term) ---------------
    const float cmaxb = (float)DIMS * esc * esc;
    const float dscale = sx * se;
    float margin_d = 8.f * sqrtf((A * se * se + sx * sx * cmaxb) * (1.f / 6.f))
                     + 0.5f * cmaxb + 1e-7f;
    float mi_f = margin_d / dscale;
    int margin_int = (mi_f > 5.0e8f) ? (1 << 29) : ((int)mi_f + 1);

    int cnt = 0;
    uint16_t* myc = s_cand + tid * CANDS;
    if (active) {
        // Prescan: warm the running max on 32 strided codes (no collect).
        int runmax = -(1 << 30);
        for (int j = 0; j < 32; j++)
            runmax = max(runmax, dotq(cbq, xq, j * 32));
        int T = runmax - margin_int;

        // Main loop: collect with running threshold.
        for (int k = 0; k < K; k++) {
            int dt = dotq(cbq, xq, k);
            if (dt >= T) {
                myc[cnt < CANDS ? cnt : CANDS - 1] = (uint16_t)k;
                cnt++;
                int nt = dt - margin_int;
                T = (nt > T) ? nt : T;
            }
        }
        // Salvage: overflow means early collects below the FINAL threshold
        // bloated the list. T now equals finalmax - margin; recollect exactly.
        if (cnt > CANDS) {
            cnt = 0;
            for (int k = 0; k < K; k++) {
                int dt = dotq(cbq, xq, k);
                if (dt >= T) {
                    myc[cnt < CANDS ? cnt : CANDS - 1] = (uint16_t)k;
                    cnt++;
                }
            }
        }
    }

    // --- Exact rescore (JAX fp32 rounding replica), output, loss -----------
    double lsum = 0.0;
    if (active) {
        float4 xr[16];
        const float4* xrow = (const float4*)(x + (size_t)n * DIMS);
#pragma unroll
        for (int j = 0; j < 16; j++) xr[j] = xrow[j];

        const bool overflow = (cnt > CANDS);   // statistically unreachable
        const int iters = overflow ? K : cnt;
        float bsc = 3.402823466e38f; int bk = 0x7fffffff;
        for (int it = 0; it < iters; it++) {
            int k = overflow ? it : (int)myc[it];
            const float4* e4 = (const float4*)(cb + (size_t)k * DIMS);
            float c = 0.f, p0 = 0.f, p1 = 0.f, p2 = 0.f, p3 = 0.f;
#pragma unroll
            for (int j = 0; j < 16; j++) {
                float4 e = e4[j];
                c = __fadd_rn(c, __fmul_rn(e.x, e.x));
                c = __fadd_rn(c, __fmul_rn(e.y, e.y));
                c = __fadd_rn(c, __fmul_rn(e.z, e.z));
                c = __fadd_rn(c, __fmul_rn(e.w, e.w));
                p0 = fmaf(xr[j].x, e.x, p0);
                p1 = fmaf(xr[j].y, e.y, p1);
                p2 = fmaf(xr[j].z, e.z, p2);
                p3 = fmaf(xr[j].w, e.w, p3);
            }
            float d = __fadd_rn(__fadd_rn(p0, p1), __fadd_rn(p2, p3));
            float s = __fadd_rn(__fsub_rn(A, 2.0f * d), c);
            if (s < bsc || (s == bsc && k < bk)) { bsc = s; bk = k; }
        }

        const float4* q4 = (const float4*)(cb + (size_t)bk * DIMS);
        float4* o4 = (float4*)(out + (size_t)n * DIMS);
        float ls = 0.f;
#pragma unroll
        for (int j = 0; j < 16; j++) {
            float4 q = q4[j];
            o4[j] = q;
            float dx = __fsub_rn(q.x, xr[j].x); ls = __fadd_rn(ls, __fmul_rn(dx, dx));
            float dy = __fsub_rn(q.y, xr[j].y); ls = __fadd_rn(ls, __fmul_rn(dy, dy));
            float dz = __fsub_rn(q.z, xr[j].z); ls = __fadd_rn(ls, __fmul_rn(dz, dz));
            float dw = __fsub_rn(q.w, xr[j].w); ls = __fadd_rn(ls, __fmul_rn(dw, dw));
        }
        lsum = (double)ls;
    }

    // --- Deterministic per-CTA fp64 reduction ------------------------------
    __syncthreads();
    red[tid] = lsum;
    __syncthreads();
    for (int s = TPB / 2; s > 0; s >>= 1) {
        if (tid < s) red[tid] += red[tid + s];
        __syncthreads();
    }
    if (tid == 0) g_partials[blockIdx.x] = red[0];
}

// --------------------------------------------------------------------------
__global__ void vq_finalize(float* __restrict__ out, int nblocks,
                            long long total, int loss_off) {
    __shared__ double r[256];
    double s = 0.0;
    for (int i = threadIdx.x; i < nblocks; i += 256) s += g_partials[i];
    r[threadIdx.x] = s;
    __syncthreads();
    for (int st = 128; st > 0; st >>= 1) {
        if (threadIdx.x < st) r[threadIdx.x] += r[threadIdx.x + st];
        __syncthreads();
    }
    if (threadIdx.x == 0) {
        float m = (float)(r[0] / (double)total);
        out[loss_off] = __fadd_rn(m, __fmul_rn(0.25f, m));
    }
}

// --------------------------------------------------------------------------
extern "C" void kernel_launch(void* const* d_in, const int* in_sizes, int n_in,
                              void* d_out, int out_size) {
    const float* x  = (const float*)d_in[0];   // [32,4096,64] fp32
    const float* cb = (const float*)d_in[1];   // [1024,64]    fp32
    float* out = (float*)d_out;

    const int ND = in_sizes[0];
    const int KD = in_sizes[1];
    const int N = ND / DIMS;
    const int K = KD / DIMS;

    int nb = (N + TPB - 1) / TPB;              // 512 CTAs for this shape
    if (nb > MAXBLOCKS) nb = MAXBLOCKS;

    const size_t smem = (size_t)K * DIMS + TPB * CANDS * 2 + TPB * 8;
    cudaFuncSetAttribute(vq_dp4a, cudaFuncAttributeMaxDynamicSharedMemorySize,
                         (int)smem);

    vq_escale_k<<<1, 256>>>(cb, KD);
    vq_dp4a<<<nb, TPB, smem>>>(x, cb, out, N, K);
    vq_finalize<<<1, 256>>>(out, nb, (long long)ND, ND);
}

// round 12
// speedup vs baseline: 3.9996x; 1.0372x over previous
#include <cuda_runtime.h>
#include <cstdint>

#define DIMS 64
#define TPB 256
#define CANDS 16
#define MAXBLOCKS 8192
#define KBLK 8

__device__ float  g_escale;
__device__ double g_partials[MAXBLOCKS];

// ---------------------------------------------------------------------------
// Kernel 1: global max |e| (deterministic fp32 max; float4 loads, high MLP).
// ---------------------------------------------------------------------------
__global__ void vq_escale_k(const float* __restrict__ cb, int KD) {
    __shared__ float r[1024];
    float m = 0.f;
    const float4* c4 = (const float4*)cb;
    for (int i = threadIdx.x; i < KD / 4; i += 1024) {
        float4 v = c4[i];
        m = fmaxf(m, fmaxf(fmaxf(fabsf(v.x), fabsf(v.y)),
                           fmaxf(fabsf(v.z), fabsf(v.w))));
    }
    r[threadIdx.x] = m;
    __syncthreads();
    for (int s = 512; s > 0; s >>= 1) {
        if (threadIdx.x < s)
            r[threadIdx.x] = fmaxf(r[threadIdx.x], r[threadIdx.x + s]);
        __syncthreads();
    }
    if (threadIdx.x == 0) g_escale = r[0];
}

// 64-dim int8 dot via 16 DP4A (exact integer arithmetic; max |acc| ~1.03e6).
__device__ __forceinline__ int dotq(const int4* __restrict__ cbq,
                                    const int xq[16], int k) {
    int s0 = 0, s1 = 0, s2 = 0, s3 = 0;
#pragma unroll
    for (int i = 0; i < 4; i++) {
        int4 v = cbq[k * 4 + i];
        s0 = __dp4a(xq[4 * i + 0], v.x, s0);
        s1 = __dp4a(xq[4 * i + 1], v.y, s1);
        s2 = __dp4a(xq[4 * i + 2], v.z, s2);
        s3 = __dp4a(xq[4 * i + 3], v.w, s3);
    }
    return (s0 + s1) + (s2 + s3);
}

// ---------------------------------------------------------------------------
// Filter: int8 DP4A d-tilde in branchless blocks of KBLK codes (one compare
// per block against the running threshold; block-entry T is conservative
// since T only rises). Overflow -> int salvage pass with final threshold;
// beyond that (statistically unreachable) -> exhaustive exact scan.
// Rescore: exact fp32 JAX-rounding replica (validated 5x: rel_err
// 4.368407e-05, zero argmin flips).
// ---------------------------------------------------------------------------
__global__ __launch_bounds__(TPB, 2)
void vq_dp4a(const float* __restrict__ x, const float* __restrict__ cb,
             float* __restrict__ out, int N, int K) {
    extern __shared__ char smem[];
    const int4* cbq   = (const int4*)smem;                  // K*64 int8
    uint16_t* s_cand  = (uint16_t*)(smem + (size_t)K * DIMS);
    double*   red     = (double*)(smem + (size_t)K * DIMS + TPB * CANDS * 2);

    const int tid = threadIdx.x;
    const int n = blockIdx.x * TPB + tid;
    const bool active = (n < N);

    const float esc = g_escale;
    const float se = fmaxf(esc, 1e-20f) / 127.f;
    const float inv_se = 1.f / se;

    // --- Quantize codebook into SMEM int8 (byte order matches xq packing) --
    for (int i = tid; i < K * (DIMS / 4); i += TPB) {
        float4 v = ((const float4*)cb)[i];
        int q0 = __float2int_rn(v.x * inv_se);
        int q1 = __float2int_rn(v.y * inv_se);
        int q2 = __float2int_rn(v.z * inv_se);
        int q3 = __float2int_rn(v.w * inv_se);
        ((int*)smem)[i] = (q0 & 255) | ((q1 & 255) << 8) |
                          ((q2 & 255) << 16) | (q3 << 24);
    }

    // --- Own point: exact-sequential A (validated order), maxabs, quantize --
    float A = 0.f, mx = 0.f;
    int xq[16];
    float sx = 1.f;
    if (active) {
        const float4* xrow = (const float4*)(x + (size_t)n * DIMS);
        float4 xr[16];
#pragma unroll
        for (int j = 0; j < 16; j++) xr[j] = xrow[j];
#pragma unroll
        for (int j = 0; j < 16; j++) {
            A = __fadd_rn(A, __fmul_rn(xr[j].x, xr[j].x));
            A = __fadd_rn(A, __fmul_rn(xr[j].y, xr[j].y));
            A = __fadd_rn(A, __fmul_rn(xr[j].z, xr[j].z));
            A = __fadd_rn(A, __fmul_rn(xr[j].w, xr[j].w));
            mx = fmaxf(mx, fmaxf(fmaxf(fabsf(xr[j].x), fabsf(xr[j].y)),
                                 fmaxf(fabsf(xr[j].z), fabsf(xr[j].w))));
        }
        sx = fmaxf(mx, 1e-20f) / 127.f;
        float inv_sx = 1.f / sx;
#pragma unroll
        for (int j = 0; j < 16; j++) {
            int q0 = __float2int_rn(xr[j].x * inv_sx);
            int q1 = __float2int_rn(xr[j].y * inv_sx);
            int q2 = __float2int_rn(xr[j].z * inv_sx);
            int q3 = __float2int_rn(xr[j].w * inv_sx);
            xq[j] = (q0 & 255) | ((q1 & 255) << 8) |
                    ((q2 & 255) << 16) | (q3 << 24);
        }
    } else {
#pragma unroll
        for (int j = 0; j < 16; j++) xq[j] = 0;
    }
    __syncthreads();

    // --- Margin in integer units (8-sigma quant-error model + ||e||^2/2) ---
    const float cmaxb = (float)DIMS * esc * esc;
    const float dscale = sx * se;
    float margin_d = 8.f * sqrtf((A * se * se + sx * sx * cmaxb) * (1.f / 6.f))
                     + 0.5f * cmaxb + 1e-7f;
    float mi_f = margin_d / dscale;
    int margin_int = (mi_f > 5.0e8f) ? (1 << 29) : ((int)mi_f + 1);

    int cnt = 0;
    uint16_t* myc = s_cand + tid * CANDS;
    if (active) {
        // Prescan: warm the running max on 32 strided codes (no collect).
        int runmax = -(1 << 30);
        for (int j = 0; j < 32; j++)
            runmax = max(runmax, dotq(cbq, xq, j * 32));
        int T = runmax - margin_int;

        // Main loop: branchless blocks of KBLK codes, one compare per block.
        for (int kb = 0; kb < K; kb += KBLK) {
            int dt[KBLK];
#pragma unroll
            for (int j = 0; j < KBLK; j++) dt[j] = dotq(cbq, xq, kb + j);
            int bm = dt[0];
#pragma unroll
            for (int j = 1; j < KBLK; j++) bm = max(bm, dt[j]);
            if (bm >= T) {                      // rare (few blocks per point)
#pragma unroll
                for (int j = 0; j < KBLK; j++) {
                    if (dt[j] >= T) {
                        myc[cnt < CANDS ? cnt : CANDS - 1] =
                            (uint16_t)(kb + j);
                        cnt++;
                        int nt = dt[j] - margin_int;
                        T = (nt > T) ? nt : T;
                    }
                }
            }
        }
        // Salvage: T is now finalmax - margin; recollect exactly on overflow.
        if (cnt > CANDS) {
            cnt = 0;
            for (int kb = 0; kb < K; kb += KBLK) {
                int dt[KBLK];
#pragma unroll
                for (int j = 0; j < KBLK; j++) dt[j] = dotq(cbq, xq, kb + j);
                int bm = dt[0];
#pragma unroll
                for (int j = 1; j < KBLK; j++) bm = max(bm, dt[j]);
                if (bm >= T) {
#pragma unroll
                    for (int j = 0; j < KBLK; j++)
                        if (dt[j] >= T) {
                            myc[cnt < CANDS ? cnt : CANDS - 1] =
                                (uint16_t)(kb + j);
                            cnt++;
                        }
                }
            }
        }
    }

    // --- Exact rescore (JAX fp32 rounding replica), output, loss -----------
    double lsum = 0.0;
    if (active) {
        float4 xr[16];
        const float4* xrow = (const float4*)(x + (size_t)n * DIMS);
#pragma unroll
        for (int j = 0; j < 16; j++) xr[j] = xrow[j];

        const bool overflow = (cnt > CANDS);   // statistically unreachable
        const int iters = overflow ? K : cnt;
        float bsc = 3.402823466e38f; int bk = 0x7fffffff;
        for (int it = 0; it < iters; it++) {
            int k = overflow ? it : (int)myc[it];
            const float4* e4 = (const float4*)(cb + (size_t)k * DIMS);
            float c = 0.f, p0 = 0.f, p1 = 0.f, p2 = 0.f, p3 = 0.f;
#pragma unroll
            for (int j = 0; j < 16; j++) {
                float4 e = e4[j];
                c = __fadd_rn(c, __fmul_rn(e.x, e.x));
                c = __fadd_rn(c, __fmul_rn(e.y, e.y));
                c = __fadd_rn(c, __fmul_rn(e.z, e.z));
                c = __fadd_rn(c, __fmul_rn(e.w, e.w));
                p0 = fmaf(xr[j].x, e.x, p0);
                p1 = fmaf(xr[j].y, e.y, p1);
                p2 = fmaf(xr[j].z, e.z, p2);
                p3 = fmaf(xr[j].w, e.w, p3);
            }
            float d = __fadd_rn(__fadd_rn(p0, p1), __fadd_rn(p2, p3));
            float s = __fadd_rn(__fsub_rn(A, 2.0f * d), c);
            if (s < bsc || (s == bsc && k < bk)) { bsc = s; bk = k; }
        }

        const float4* q4 = (const float4*)(cb + (size_t)bk * DIMS);
        float4* o4 = (float4*)(out + (size_t)n * DIMS);
        float ls = 0.f;
#pragma unroll
        for (int j = 0; j < 16; j++) {
            float4 q = q4[j];
            o4[j] = q;
            float dx = __fsub_rn(q.x, xr[j].x); ls = __fadd_rn(ls, __fmul_rn(dx, dx));
            float dy = __fsub_rn(q.y, xr[j].y); ls = __fadd_rn(ls, __fmul_rn(dy, dy));
            float dz = __fsub_rn(q.z, xr[j].z); ls = __fadd_rn(ls, __fmul_rn(dz, dz));
            float dw = __fsub_rn(q.w, xr[j].w); ls = __fadd_rn(ls, __fmul_rn(dw, dw));
        }
        lsum = (double)ls;
    }

    // --- Deterministic per-CTA fp64 reduction ------------------------------
    __syncthreads();
    red[tid] = lsum;
    __syncthreads();
    for (int s = TPB / 2; s > 0; s >>= 1) {
        if (tid < s) red[tid] += red[tid + s];
        __syncthreads();
    }
    if (tid == 0) g_partials[blockIdx.x] = red[0];
}

// --------------------------------------------------------------------------
__global__ void vq_finalize(float* __restrict__ out, int nblocks,
                            long long total, int loss_off) {
    __shared__ double r[256];
    double s = 0.0;
    for (int i = threadIdx.x; i < nblocks; i += 256) s += g_partials[i];
    r[threadIdx.x] = s;
    __syncthreads();
    for (int st = 128; st > 0; st >>= 1) {
        if (threadIdx.x < st) r[threadIdx.x] += r[threadIdx.x + st];
        __syncthreads();
    }
    if (threadIdx.x == 0) {
        float m = (float)(r[0] / (double)total);
        out[loss_off] = __fadd_rn(m, __fmul_rn(0.25f, m));
    }
}

// --------------------------------------------------------------------------
extern "C" void kernel_launch(void* const* d_in, const int* in_sizes, int n_in,
                              void* d_out, int out_size) {
    const float* x  = (const float*)d_in[0];   // [32,4096,64] fp32
    const float* cb = (const float*)d_in[1];   // [1024,64]    fp32
    float* out = (float*)d_out;

    const int ND = in_sizes[0];
    const int KD = in_sizes[1];
    const int N = ND / DIMS;
    const int K = KD / DIMS;

    int nb = (N + TPB - 1) / TPB;              // 512 CTAs for this shape
    if (nb > MAXBLOCKS) nb = MAXBLOCKS;

    const size_t smem = (size_t)K * DIMS + TPB * CANDS * 2 + TPB * 8;
    cudaFuncSetAttribute(vq_dp4a, cudaFuncAttributeMaxDynamicSharedMemorySize,
                         (int)smem);

    vq_escale_k<<<1, 1024>>>(cb, KD);
    vq_dp4a<<<nb, TPB, smem>>>(x, cb, out, N, K);
    vq_finalize<<<1, 256>>>(out, nb, (long long)ND, ND);
}

// round 16
// speedup vs baseline: 4.4287x; 1.1073x over previous
#include <cuda_runtime.h>
#include <cstdint>

#define DIMS 64
#define TPB 256
#define CANDS 32
#define MAXBLOCKS 8192
#define KBLK 8
#define ESC_CTAS 8

__device__ float        g_esc_part[ESC_CTAS];
__device__ double       g_partials[MAXBLOCKS];
__device__ unsigned int g_done;            // reset by last CTA each launch

// ---------------------------------------------------------------------------
// Kernel 1: partial max |e| over 8 CTAs (per-slot deterministic).
// ---------------------------------------------------------------------------
__global__ void vq_esc8(const float* __restrict__ cb, int KD) {
    __shared__ float r[256];
    const float4* c4 = (const float4*)cb;
    const int nf4 = KD / 4;
    float m = 0.f;
    for (int i = blockIdx.x * 256 + threadIdx.x; i < nf4; i += ESC_CTAS * 256) {
        float4 v = c4[i];
        m = fmaxf(m, fmaxf(fmaxf(fabsf(v.x), fabsf(v.y)),
                           fmaxf(fabsf(v.z), fabsf(v.w))));
    }
    r[threadIdx.x] = m;
    __syncthreads();
    for (int s = 128; s > 0; s >>= 1) {
        if (threadIdx.x < s)
            r[threadIdx.x] = fmaxf(r[threadIdx.x], r[threadIdx.x + s]);
        __syncthreads();
    }
    if (threadIdx.x == 0) g_esc_part[blockIdx.x] = r[0];
}

// 64-dim int8 dot via 16 DP4A (exact integer arithmetic; max |acc| ~1.03e6).
__device__ __forceinline__ int dotq(const int4* __restrict__ cbq,
                                    const int xq[16], int k) {
    int s0 = 0, s1 = 0, s2 = 0, s3 = 0;
#pragma unroll
    for (int i = 0; i < 4; i++) {
        int4 v = cbq[k * 4 + i];
        s0 = __dp4a(xq[4 * i + 0], v.x, s0);
        s1 = __dp4a(xq[4 * i + 1], v.y, s1);
        s2 = __dp4a(xq[4 * i + 2], v.z, s2);
        s3 = __dp4a(xq[4 * i + 3], v.w, s3);
    }
    return (s0 + s1) + (s2 + s3);
}

// ---------------------------------------------------------------------------
// Fused: int8 DP4A filter (branchless KBLK blocks, running threshold,
// CANDS=32 so salvage is ~never taken) + exact fp32 JAX-rounding rescore
// (validated 6x: rel_err 4.368407e-05, zero argmin flips) + loss with
// last-CTA-elected final reduction replicating the old finalize bit-exactly.
// ---------------------------------------------------------------------------
__global__ __launch_bounds__(TPB, 2)
void vq_dp4a(const float* __restrict__ x, const float* __restrict__ cb,
             float* __restrict__ out, int N, int K) {
    extern __shared__ char smem[];
    const int4* cbq  = (const int4*)smem;                   // K*64 int8
    uint16_t* s_cand = (uint16_t*)(smem + (size_t)K * DIMS);
    double*   red    = (double*)(smem + (size_t)K * DIMS);  // overlays cand
    __shared__ unsigned int s_last;

    const int tid = threadIdx.x;
    const int n = blockIdx.x * TPB + tid;
    const bool active = (n < N);

    float esc = 0.f;
#pragma unroll
    for (int i = 0; i < ESC_CTAS; i++) esc = fmaxf(esc, g_esc_part[i]);
    const float se = fmaxf(esc, 1e-20f) / 127.f;
    const float inv_se = 1.f / se;

    // --- Quantize codebook into SMEM int8 (byte order matches xq packing) --
    for (int i = tid; i < K * (DIMS / 4); i += TPB) {
        float4 v = ((const float4*)cb)[i];
        int q0 = __float2int_rn(v.x * inv_se);
        int q1 = __float2int_rn(v.y * inv_se);
        int q2 = __float2int_rn(v.z * inv_se);
        int q3 = __float2int_rn(v.w * inv_se);
        ((int*)smem)[i] = (q0 & 255) | ((q1 & 255) << 8) |
                          ((q2 & 255) << 16) | (q3 << 24);
    }

    // --- Own point: exact-sequential A (validated order), maxabs, quantize --
    float A = 0.f, mx = 0.f;
    int xq[16];
    float sx = 1.f;
    if (active) {
        const float4* xrow = (const float4*)(x + (size_t)n * DIMS);
        float4 xr[16];
#pragma unroll
        for (int j = 0; j < 16; j++) xr[j] = xrow[j];
#pragma unroll
        for (int j = 0; j < 16; j++) {
            A = __fadd_rn(A, __fmul_rn(xr[j].x, xr[j].x));
            A = __fadd_rn(A, __fmul_rn(xr[j].y, xr[j].y));
            A = __fadd_rn(A, __fmul_rn(xr[j].z, xr[j].z));
            A = __fadd_rn(A, __fmul_rn(xr[j].w, xr[j].w));
            mx = fmaxf(mx, fmaxf(fmaxf(fabsf(xr[j].x), fabsf(xr[j].y)),
                                 fmaxf(fabsf(xr[j].z), fabsf(xr[j].w))));
        }
        sx = fmaxf(mx, 1e-20f) / 127.f;
        float inv_sx = 1.f / sx;
#pragma unroll
        for (int j = 0; j < 16; j++) {
            int q0 = __float2int_rn(xr[j].x * inv_sx);
            int q1 = __float2int_rn(xr[j].y * inv_sx);
            int q2 = __float2int_rn(xr[j].z * inv_sx);
            int q3 = __float2int_rn(xr[j].w * inv_sx);
            xq[j] = (q0 & 255) | ((q1 & 255) << 8) |
                    ((q2 & 255) << 16) | (q3 << 24);
        }
    } else {
#pragma unroll
        for (int j = 0; j < 16; j++) xq[j] = 0;
    }
    __syncthreads();

    // --- Margin in integer units (8-sigma quant-error model + ||e||^2/2) ---
    const float cmaxb = (float)DIMS * esc * esc;
    const float dscale = sx * se;
    float margin_d = 8.f * sqrtf((A * se * se + sx * sx * cmaxb) * (1.f / 6.f))
                     + 0.5f * cmaxb + 1e-7f;
    float mi_f = margin_d / dscale;
    int margin_int = (mi_f > 5.0e8f) ? (1 << 29) : ((int)mi_f + 1);

    int cnt = 0;
    uint16_t* myc = s_cand + tid * CANDS;
    if (active) {
        // Prescan: warm the running max on 32 strided codes (no collect).
        int runmax = -(1 << 30);
        for (int j = 0; j < 32; j++)
            runmax = max(runmax, dotq(cbq, xq, j * 32));
        int T = runmax - margin_int;

        // Main loop: branchless blocks, one threshold compare per block.
        for (int kb = 0; kb < K; kb += KBLK) {
            int dt[KBLK];
#pragma unroll
            for (int j = 0; j < KBLK; j++) dt[j] = dotq(cbq, xq, kb + j);
            int bm = dt[0];
#pragma unroll
            for (int j = 1; j < KBLK; j++) bm = max(bm, dt[j]);
            if (bm >= T) {
#pragma unroll
                for (int j = 0; j < KBLK; j++) {
                    if (dt[j] >= T) {
                        myc[cnt < CANDS ? cnt : CANDS - 1] =
                            (uint16_t)(kb + j);
                        cnt++;
                        int nt = dt[j] - margin_int;
                        T = (nt > T) ? nt : T;
                    }
                }
            }
        }
        // Salvage (P ~ 1e-6 at CANDS=32): recollect with final threshold.
        if (cnt > CANDS) {
            cnt = 0;
            for (int kb = 0; kb < K; kb += KBLK) {
                int dt[KBLK];
#pragma unroll
                for (int j = 0; j < KBLK; j++) dt[j] = dotq(cbq, xq, kb + j);
                int bm = dt[0];
#pragma unroll
                for (int j = 1; j < KBLK; j++) bm = max(bm, dt[j]);
                if (bm >= T) {
#pragma unroll
                    for (int j = 0; j < KBLK; j++)
                        if (dt[j] >= T) {
                            myc[cnt < CANDS ? cnt : CANDS - 1] =
                                (uint16_t)(kb + j);
                            cnt++;
                        }
                }
            }
        }
    }

    // --- Exact rescore (JAX fp32 rounding replica), output, loss -----------
    double lsum = 0.0;
    if (active) {
        float4 xr[16];
        const float4* xrow = (const float4*)(x + (size_t)n * DIMS);
#pragma unroll
        for (int j = 0; j < 16; j++) xr[j] = xrow[j];
        float A2 = 0.f;
#pragma unroll
        for (int j = 0; j < 16; j++) {
            A2 = __fadd_rn(A2, __fmul_rn(xr[j].x, xr[j].x));
            A2 = __fadd_rn(A2, __fmul_rn(xr[j].y, xr[j].y));
            A2 = __fadd_rn(A2, __fmul_rn(xr[j].z, xr[j].z));
            A2 = __fadd_rn(A2, __fmul_rn(xr[j].w, xr[j].w));
        }
        const bool overflow = (cnt > CANDS);   // statistically unreachable
        const int iters = overflow ? K : cnt;
        float bsc = 3.402823466e38f; int bk = 0x7fffffff;
        for (int it = 0; it < iters; it++) {
            int k = overflow ? it : (int)myc[it];
            const float4* e4 = (const float4*)(cb + (size_t)k * DIMS);
            float c = 0.f, p0 = 0.f, p1 = 0.f, p2 = 0.f, p3 = 0.f;
#pragma unroll
            for (int j = 0; j < 16; j++) {
                float4 e = e4[j];
                c = __fadd_rn(c, __fmul_rn(e.x, e.x));
                c = __fadd_rn(c, __fmul_rn(e.y, e.y));
                c = __fadd_rn(c, __fmul_rn(e.z, e.z));
                c = __fadd_rn(c, __fmul_rn(e.w, e.w));
                p0 = fmaf(xr[j].x, e.x, p0);
                p1 = fmaf(xr[j].y, e.y, p1);
                p2 = fmaf(xr[j].z, e.z, p2);
                p3 = fmaf(xr[j].w, e.w, p3);
            }
            float d = __fadd_rn(__fadd_rn(p0, p1), __fadd_rn(p2, p3));
            float s = __fadd_rn(__fsub_rn(A2, 2.0f * d), c);
            if (s < bsc || (s == bsc && k < bk)) { bsc = s; bk = k; }
        }

        const float4* q4 = (const float4*)(cb + (size_t)bk * DIMS);
        float4* o4 = (float4*)(out + (size_t)n * DIMS);
        float ls = 0.f;
#pragma unroll
        for (int j = 0; j < 16; j++) {
            float4 q = q4[j];
            o4[j] = q;
            float dx = __fsub_rn(q.x, xr[j].x); ls = __fadd_rn(ls, __fmul_rn(dx, dx));
            float dy = __fsub_rn(q.y, xr[j].y); ls = __fadd_rn(ls, __fmul_rn(dy, dy));
            float dz = __fsub_rn(q.z, xr[j].z); ls = __fadd_rn(ls, __fmul_rn(dz, dz));
            float dw = __fsub_rn(q.w, xr[j].w); ls = __fadd_rn(ls, __fmul_rn(dw, dw));
        }
        lsum = (double)ls;
    }

    // --- Per-CTA fp64 reduction (cand region now dead; red overlays it) ----
    __syncthreads();
    red[tid] = lsum;
    __syncthreads();
    for (int s = TPB / 2; s > 0; s >>= 1) {
        if (tid < s) red[tid] += red[tid + s];
        __syncthreads();
    }
    if (tid == 0) g_partials[blockIdx.x] = red[0];

    // --- Last-CTA election: final reduction, bit-identical to old finalize -
    if (tid == 0) {
        __threadfence();
        unsigned int d = atomicAdd(&g_done, 1u);
        s_last = (d == gridDim.x - 1) ? 1u : 0u;
    }
    __syncthreads();
    if (s_last) {
        __threadfence();
        double s = 0.0;
        for (int i = tid; i < (int)gridDim.x; i += 256) s += g_partials[i];
        red[tid] = s;
        __syncthreads();
        for (int st = 128; st > 0; st >>= 1) {
            if (tid < st) red[tid] += red[tid + st];
            __syncthreads();
        }
        if (tid == 0) {
            long long total = (long long)N * DIMS;
            float m = (float)(red[0] / (double)total);
            out[(size_t)N * DIMS] = __fadd_rn(m, __fmul_rn(0.25f, m));
            g_done = 0;                        // reset for graph replay
        }
    }
}

// --------------------------------------------------------------------------
extern "C" void kernel_launch(void* const* d_in, const int* in_sizes, int n_in,
                              void* d_out, int out_size) {
    const float* x  = (const float*)d_in[0];   // [32,4096,64] fp32
    const float* cb = (const float*)d_in[1];   // [1024,64]    fp32
    float* out = (float*)d_out;

    const int ND = in_sizes[0];
    const int KD = in_sizes[1];
    const int N = ND / DIMS;
    const int K = KD / DIMS;

    int nb = (N + TPB - 1) / TPB;              // 512 CTAs for this shape
    if (nb > MAXBLOCKS) nb = MAXBLOCKS;

    const size_t smem = (size_t)K * DIMS + TPB * CANDS * 2;   // 80 KB
    cudaFuncSetAttribute(vq_dp4a, cudaFuncAttributeMaxDynamicSharedMemorySize,
                         (int)smem);

    vq_esc8<<<ESC_CTAS, 256>>>(cb, KD);
    vq_dp4a<<<nb, TPB, smem>>>(x, cb, out, N, K);
}